// round 15
// baseline (speedup 1.0000x reference)
#include <cuda_runtime.h>
#include <cstdint>

#define D_MODEL 1024
#define NHEAD   16
#define DKH     64
#define BATCH   8
#define SEQ     1024
#define MROWS   (BATCH*SEQ)                   // 8192
#define OUT_ELEMS  (MROWS*D_MODEL)            // 8388608
#define ATTN_ELEMS (BATCH*NHEAD*SEQ*SEQ)      // 134217728
#define NROWS_TOT  (BATCH*NHEAD*SEQ)          // 131072 attention rows

// ---------------- scratch (no cudaMalloc allowed) ----------------
__device__ float g_q  [MROWS*D_MODEL];
__device__ float g_k  [MROWS*D_MODEL];
__device__ float g_v  [MROWS*D_MODEL];
__device__ float g_ctx[MROWS*D_MODEL];
__device__ float2 g_rowstat[NROWS_TOT];       // per row (M, 1/S)
__device__ float g_xt [3*MROWS*D_MODEL];      // tf32(q,k,v inputs)
__device__ float g_wt [4*D_MODEL*D_MODEL];    // tf32(Wq,Wk,Wv,Wo)
__device__ float g_ctxt[MROWS*D_MODEL];       // tf32(ctx)

// ---------------- helpers ----------------
__device__ __forceinline__ unsigned f2tf32(float f){
  unsigned r; asm("cvt.rna.tf32.f32 %0, %1;" : "=r"(r) : "f"(f)); return r;
}
__device__ __forceinline__ uint32_t smem_u32(const void* p){
  return (uint32_t)__cvta_generic_to_shared(p);
}
__device__ __forceinline__ void ldsm4(unsigned &r0, unsigned &r1, unsigned &r2, unsigned &r3, uint32_t a){
  asm volatile("ldmatrix.sync.aligned.m8n8.x4.shared.b16 {%0,%1,%2,%3}, [%4];"
    : "=r"(r0),"=r"(r1),"=r"(r2),"=r"(r3) : "r"(a));
}
__device__ __forceinline__ void mma_tf32(float &d0,float &d1,float &d2,float &d3,
    unsigned a0,unsigned a1,unsigned a2,unsigned a3, unsigned b0,unsigned b1){
  asm volatile("mma.sync.aligned.m16n8k8.row.col.f32.tf32.tf32.f32 "
    "{%0,%1,%2,%3}, {%4,%5,%6,%7}, {%8,%9}, {%0,%1,%2,%3};"
    : "+f"(d0),"+f"(d1),"+f"(d2),"+f"(d3)
    : "r"(a0),"r"(a1),"r"(a2),"r"(a3),"r"(b0),"r"(b1));
}
#define CP_ASYNC16(dst, src) \
  asm volatile("cp.async.ca.shared.global [%0], [%1], 16;" :: "r"(dst), "l"(src))
#define CP_COMMIT() asm volatile("cp.async.commit_group;" ::: "memory")
#define CP_WAIT0()  asm volatile("cp.async.wait_group 0;" ::: "memory")
// FFMA-only exp (avoids MUFU rt=8 for 134M exps). Valid for x <= 0 after max-sub.
__device__ __forceinline__ float fast_exp(float x){
  x = fmaxf(x, -80.f);
  float z  = fmaf(x, 1.4426950408889634f, 12582912.f);
  int   n  = __float_as_int(z) - 0x4B400000;
  float fn = z - 12582912.f;
  float t  = fmaf(x, 1.4426950408889634f, -fn);
  float u  = t * 0.6931471805599453f;
  float p  = fmaf(u, 0.0083333333f, 0.0416666667f);
  p = fmaf(u, p, 0.1666666667f);
  p = fmaf(u, p, 0.5f);
  p = fmaf(u, p, 1.0f);
  p = fmaf(u, p, 1.0f);
  return __int_as_float((n + 127) << 23) * p;
}

// ================= operand pre-conversion to tf32 bits =================
__global__ void cvt_x_kernel(const float* __restrict__ q, const float* __restrict__ k,
                             const float* __restrict__ v)
{
  const int z = blockIdx.y;
  const float4* src = (const float4*)(z == 0 ? q : (z == 1 ? k : v));
  uint4* dst = (uint4*)g_xt + (size_t)z * (MROWS*D_MODEL/4);
  int i = blockIdx.x*256 + threadIdx.x;          // grid.x = 8192 exact
  float4 s = src[i];
  dst[i] = make_uint4(f2tf32(s.x), f2tf32(s.y), f2tf32(s.z), f2tf32(s.w));
}

__global__ void cvt_w_kernel(const float* __restrict__ Wq, const float* __restrict__ Wk,
                             const float* __restrict__ Wv, const float* __restrict__ Wo)
{
  const int z = blockIdx.y;
  const float4* src = (const float4*)(z == 0 ? Wq : (z == 1 ? Wk : (z == 2 ? Wv : Wo)));
  uint4* dst = (uint4*)g_wt + (size_t)z * (D_MODEL*D_MODEL/4);
  int i = blockIdx.x*256 + threadIdx.x;          // grid.x = 1024 exact
  float4 s = src[i];
  dst[i] = make_uint4(f2tf32(s.x), f2tf32(s.y), f2tf32(s.z), f2tf32(s.w));
}

__global__ void cvt_c_kernel()
{
  const float4* src = (const float4*)g_ctx;
  uint4* dst = (uint4*)g_ctxt;
  int i = blockIdx.x*256 + threadIdx.x;          // grid.x = 8192 exact
  float4 s = src[i];
  dst[i] = make_uint4(f2tf32(s.x), f2tf32(s.y), f2tf32(s.z), f2tf32(s.w));
}

// ================= TF32 GEMM v3: cp.async mainloop on pre-converted operands ==========
// C[8192,1024] = A @ W^T + bias. CTA tile 128x128, 128 threads, 4 warps of 64x64.
// No in-loop cvt, no fill STS, no register prefetch (R14 post-mortem: regs 254 -> spills).
#define GBM 128
#define GBN 128
#define GBK 32
#define GPAD 36
#define GEMM_SMEM_BYTES (4*GBM*GPAD*4)
#define GK 1024
#define GN 1024

__device__ __forceinline__ void gemm_body(const float* __restrict__ A,
                                          const float* __restrict__ W,
                                          const float* __restrict__ bias,
                                          float* __restrict__ C, float* sm)
{
  float* As = sm;                                 // [2][128][36]
  float* Ws = sm + 2*GBM*GPAD;                    // [2][128][36]
  const int tid = threadIdx.x, lane = tid & 31, wid = tid >> 5;
  const int wr = wid & 1, wc = wid >> 1;          // 2x2 warp grid, warp tile 64x64
  const int bm0 = blockIdx.y * GBM, bn0 = blockIdx.x * GBN;
  const int qg = lane >> 3, lr = lane & 7;
  const int aRow = wr*64 + (qg & 1)*8 + lr;       // + mt*16, mt 0..3
  const int aCol = (qg >> 1)*4;
  const int bRow = wc*64 + (qg >> 1)*8 + lr;      // + np*16, np 0..3
  const int bCol = (qg & 1)*4;

  float acc[4][8][4];
  #pragma unroll
  for (int mt = 0; mt < 4; mt++)
    #pragma unroll
    for (int nt = 0; nt < 8; nt++)
      #pragma unroll
      for (int j = 0; j < 4; j++) acc[mt][nt][j] = 0.f;

  const float* Arow = A + (size_t)(bm0 + tid)*GK; // thread owns one row of each tile
  const float* Wrow = W + (size_t)(bn0 + tid)*GK;
  const uint32_t aD0 = smem_u32(As) + (uint32_t)tid*GPAD*4;
  const uint32_t wD0 = smem_u32(Ws) + (uint32_t)tid*GPAD*4;
  const int nT = GK / GBK;

  // prologue: stage 0
  #pragma unroll
  for (int i = 0; i < 8; i++) {
    CP_ASYNC16(aD0 + i*16, Arow + i*4);
    CP_ASYNC16(wD0 + i*16, Wrow + i*4);
  }
  CP_COMMIT();

  for (int t = 0; t < nT; t++) {
    CP_WAIT0();
    __syncthreads();                              // stage t data visible CTA-wide
    if (t + 1 < nT) {                             // issue stage t+1 (overlaps mma)
      const int k0 = (t + 1)*GBK;
      const uint32_t ad = aD0 + ((t + 1) & 1)*GBM*GPAD*4;
      const uint32_t wd = wD0 + ((t + 1) & 1)*GBM*GPAD*4;
      #pragma unroll
      for (int i = 0; i < 8; i++) {
        CP_ASYNC16(ad + i*16, Arow + k0 + i*4);
        CP_ASYNC16(wd + i*16, Wrow + k0 + i*4);
      }
      CP_COMMIT();
    }
    uint32_t asb = smem_u32(As + (t & 1)*GBM*GPAD);
    uint32_t wsb = smem_u32(Ws + (t & 1)*GBM*GPAD);
    #pragma unroll
    for (int kk = 0; kk < 4; kk++) {
      unsigned af[4][4];
      #pragma unroll
      for (int mt = 0; mt < 4; mt++)
        ldsm4(af[mt][0], af[mt][1], af[mt][2], af[mt][3],
              asb + ((unsigned)((aRow + mt*16)*GPAD + aCol + kk*8) << 2));
      unsigned bf[8][2];
      #pragma unroll
      for (int np = 0; np < 4; np++) {
        unsigned r0, r1, r2, r3;
        ldsm4(r0, r1, r2, r3, wsb + ((unsigned)((bRow + np*16)*GPAD + bCol + kk*8) << 2));
        bf[2*np][0]=r0; bf[2*np][1]=r1; bf[2*np+1][0]=r2; bf[2*np+1][1]=r3;
      }
      #pragma unroll
      for (int mt = 0; mt < 4; mt++)
        #pragma unroll
        for (int nt = 0; nt < 8; nt++)
          mma_tf32(acc[mt][nt][0], acc[mt][nt][1], acc[mt][nt][2], acc[mt][nt][3],
                   af[mt][0], af[mt][1], af[mt][2], af[mt][3], bf[nt][0], bf[nt][1]);
    }
  }

  #pragma unroll
  for (int mt = 0; mt < 4; mt++)
    #pragma unroll
    for (int nt = 0; nt < 8; nt++) {
      int r = bm0 + wr*64 + mt*16 + (lane >> 2);
      int c = bn0 + wc*64 + nt*8 + (lane & 3)*2;
      float2 bb = *(const float2*)(bias + c);
      float2 v0 = make_float2(acc[mt][nt][0] + bb.x, acc[mt][nt][1] + bb.y);
      float2 v1 = make_float2(acc[mt][nt][2] + bb.x, acc[mt][nt][3] + bb.y);
      *(float2*)(C + (size_t)r*GN + c)       = v0;
      *(float2*)(C + (size_t)(r + 8)*GN + c) = v1;
    }
}

__global__ void __launch_bounds__(128, 2)
gemm_tf32_kernel(const float* __restrict__ At, const float* __restrict__ Wt,
                 const float* __restrict__ bias, float* __restrict__ C)
{
  extern __shared__ float sm[];
  gemm_body(At, Wt, bias, C, sm);
}

// QKV fused: blockIdx.z selects which projection; operands from g_xt/g_wt.
__global__ void __launch_bounds__(128, 2)
qkv_gemm_kernel(const float* __restrict__ xt, const float* __restrict__ wt,
                const float* __restrict__ bq, const float* __restrict__ bk,
                const float* __restrict__ bv,
                float* __restrict__ Cq, float* __restrict__ Ck, float* __restrict__ Cv)
{
  extern __shared__ float sm[];
  const int z = blockIdx.z;
  const float* A = xt + (size_t)z*MROWS*GK;
  const float* W = wt + (size_t)z*GN*GK;
  const float* bias = (z == 0) ? bq : (z == 1 ? bk : bv);
  float* C = (z == 0) ? Cq : (z == 1 ? Ck : Cv);
  gemm_body(A, W, bias, C, sm);
}

// ======== stats2 (UNCHANGED from passing R13/R14): per-row softmax stats ========
#define S2_PAD 68
#define S2_RED (2*128*S2_PAD)               // mp[256] then sp[256]
#define S2_SMEM ((S2_RED + 512)*4)          // 71,680 B

__global__ __launch_bounds__(256)
void stats2_kernel(const float* __restrict__ Qp, const float* __restrict__ Kp)
{
  extern __shared__ float sm[];
  float* Qs = sm;                     // [128][68] q-rows (pre-scaled 1/8), tf32
  float* Ks = sm + 128*S2_PAD;        // [128][68] k-chunk rows, tf32
  float* mp = sm + S2_RED;            // [256]
  float* sp = mp + 256;               // [256]
  const int tid = threadIdx.x, lane = tid & 31, wid = tid >> 5;
  const int wr = wid & 3, wc = wid >> 2;
  const int bh = blockIdx.y, b = bh >> 4, h = bh & 15;
  const int bm0 = blockIdx.x * 128;
  const int qg = lane >> 3, lr = lane & 7;
  const int aRow = wr*32 + (qg & 1)*8 + lr;
  const int aCol = (qg >> 1)*4;
  const int bRow = wc*64 + (qg >> 1)*8 + lr;
  const int bCol = (qg & 1)*4;

  #pragma unroll
  for (int i = 0; i < 8; i++) {
    int f4 = i*256 + tid; int r = f4 >> 4; int c = (f4 & 15) << 2;
    float4 v = *(const float4*)(Qp + (size_t)(b*SEQ + bm0 + r)*D_MODEL + h*DKH + c);
    uint4 u; u.x=f2tf32(0.125f*v.x); u.y=f2tf32(0.125f*v.y);
             u.z=f2tf32(0.125f*v.z); u.w=f2tf32(0.125f*v.w);
    *(uint4*)(Qs + r*S2_PAD + c) = u;
  }

  float runM = -1e30f, runS = 0.f;    // threads tid<128 own row `tid`
  uint32_t qsb = smem_u32(Qs), ksb = smem_u32(Ks);

  for (int ch = 0; ch < 8; ch++) {
    __syncthreads();
    #pragma unroll
    for (int i = 0; i < 8; i++) {
      int f4 = i*256 + tid; int r = f4 >> 4; int c = (f4 & 15) << 2;
      float4 v = *(const float4*)(Kp + (size_t)(b*SEQ + ch*128 + r)*D_MODEL + h*DKH + c);
      uint4 u; u.x=f2tf32(v.x); u.y=f2tf32(v.y); u.z=f2tf32(v.z); u.w=f2tf32(v.w);
      *(uint4*)(Ks + r*S2_PAD + c) = u;
    }
    __syncthreads();

    float acc[2][8][4];
    #pragma unroll
    for (int mt = 0; mt < 2; mt++)
      #pragma unroll
      for (int nt = 0; nt < 8; nt++)
        #pragma unroll
        for (int j = 0; j < 4; j++) acc[mt][nt][j] = 0.f;

    #pragma unroll
    for (int kk = 0; kk < 8; kk++) {
      unsigned af[2][4];
      #pragma unroll
      for (int mt = 0; mt < 2; mt++)
        ldsm4(af[mt][0], af[mt][1], af[mt][2], af[mt][3],
              qsb + ((unsigned)((aRow + mt*16)*S2_PAD + aCol + kk*8) << 2));
      unsigned bf[8][2];
      #pragma unroll
      for (int np = 0; np < 4; np++) {
        unsigned r0, r1, r2, r3;
        ldsm4(r0, r1, r2, r3, ksb + ((unsigned)((bRow + np*16)*S2_PAD + bCol + kk*8) << 2));
        bf[2*np][0]=r0; bf[2*np][1]=r1; bf[2*np+1][0]=r2; bf[2*np+1][1]=r3;
      }
      #pragma unroll
      for (int mt = 0; mt < 2; mt++)
        #pragma unroll
        for (int nt = 0; nt < 8; nt++)
          mma_tf32(acc[mt][nt][0], acc[mt][nt][1], acc[mt][nt][2], acc[mt][nt][3],
                   af[mt][0], af[mt][1], af[mt][2], af[mt][3], bf[nt][0], bf[nt][1]);
    }

    #pragma unroll
    for (int mt = 0; mt < 2; mt++)
      #pragma unroll
      for (int hh = 0; hh < 2; hh++) {
        float m = -1e30f;
        #pragma unroll
        for (int nt = 0; nt < 8; nt++)
          m = fmaxf(m, fmaxf(acc[mt][nt][2*hh], acc[mt][nt][2*hh+1]));
        #pragma unroll
        for (int off = 1; off <= 2; off <<= 1)
          m = fmaxf(m, __shfl_xor_sync(0xffffffffu, m, off));
        if ((lane & 3) == 0)
          mp[wc*128 + wr*32 + mt*16 + hh*8 + (lane >> 2)] = m;
      }
    __syncthreads();
    #pragma unroll
    for (int mt = 0; mt < 2; mt++)
      #pragma unroll
      for (int hh = 0; hh < 2; hh++) {
        int rl = wr*32 + mt*16 + hh*8 + (lane >> 2);
        float m = fmaxf(mp[rl], mp[128 + rl]);
        float s = 0.f;
        #pragma unroll
        for (int nt = 0; nt < 8; nt++)
          s += fast_exp(acc[mt][nt][2*hh] - m) + fast_exp(acc[mt][nt][2*hh+1] - m);
        #pragma unroll
        for (int off = 1; off <= 2; off <<= 1)
          s += __shfl_xor_sync(0xffffffffu, s, off);
        if ((lane & 3) == 0) sp[wc*128 + rl] = s;
      }
    __syncthreads();
    if (tid < 128) {
      float m_c = fmaxf(mp[tid], mp[128 + tid]);
      float s_c = sp[tid] + sp[128 + tid];
      float Mn  = fmaxf(runM, m_c);
      runS = runS * fast_exp(runM - Mn) + s_c * fast_exp(m_c - Mn);
      runM = Mn;
    }
  }

  if (tid < 128)
    g_rowstat[(size_t)bh*SEQ + bm0 + tid] = make_float2(runM, 1.f / runS);
}

// ======== fused apv (UNCHANGED from passing R11/R13/R14) ========
#define AP_PAD 68
#define AP_Q   0
#define AP_K   (128*AP_PAD)
#define AP_V   (AP_K + 64*AP_PAD)
#define AP_P   (AP_V + 64*AP_PAD)
#define AP_RST (AP_P + 128*AP_PAD)
#define APV_SMEM ((AP_RST + 256)*4)       // 105,472 B

__global__ void __launch_bounds__(256, 2)
apv_kernel(const float* __restrict__ Qp, const float* __restrict__ Kp,
           const float* __restrict__ Vp,
           float* __restrict__ attn, float* __restrict__ ctx)
{
  extern __shared__ float sm[];
  float*  Qs  = sm + AP_Q;
  float*  Kc  = sm + AP_K;
  float*  Vt  = sm + AP_V;
  float*  Ps  = sm + AP_P;
  float2* rst = (float2*)(sm + AP_RST);
  const int tid = threadIdx.x, lane = tid & 31, wid = tid >> 5;
  const int bh = blockIdx.y, b = bh >> 4, h = bh & 15;
  const int bm0 = blockIdx.x * 128;
  const int qg = lane >> 3, lr = lane & 7;
  const int qd = lane & 3;
  const int wr = wid & 3, wc = wid >> 2;
  const int aRowQ = wr*32 + (qg & 1)*8 + lr;
  const int aCol  = (qg >> 1)*4;
  const int bRowK = wc*32 + (qg >> 1)*8 + lr;
  const int bColK = (qg & 1)*4;
  const int bRowV = (qg >> 1)*8 + lr;
  const int bColV = (qg & 1)*4;
  const int vn  = tid & 63;
  const int vk0 = (tid >> 6) * 16;

  if (tid < 128) rst[tid] = g_rowstat[(size_t)bh*SEQ + bm0 + tid];

  #pragma unroll
  for (int i = 0; i < 8; i++) {
    int f4 = i*256 + tid; int r = f4 >> 4; int c = (f4 & 15) << 2;
    float4 v = *(const float4*)(Qp + (size_t)(b*SEQ + bm0 + r)*D_MODEL + h*DKH + c);
    uint4 u; u.x=f2tf32(0.125f*v.x); u.y=f2tf32(0.125f*v.y);
             u.z=f2tf32(0.125f*v.z); u.w=f2tf32(0.125f*v.w);
    *(uint4*)(Qs + r*AP_PAD + c) = u;
  }

  float* Abase = attn + (size_t)bh*SEQ*SEQ + (size_t)bm0*SEQ;
  const float* Vcol = Vp + (size_t)(b*SEQ)*D_MODEL + h*DKH + vn;

  float oacc[2][4][4];
  #pragma unroll
  for (int mt = 0; mt < 2; mt++)
    #pragma unroll
    for (int nt = 0; nt < 4; nt++)
      #pragma unroll
      for (int j = 0; j < 4; j++) oacc[mt][nt][j] = 0.f;

  uint32_t qsb = smem_u32(Qs), kcb = smem_u32(Kc), vtb = smem_u32(Vt), psb = smem_u32(Ps);

  for (int ch = 0; ch < 16; ch++) {
    __syncthreads();
    #pragma unroll
    for (int i = 0; i < 4; i++) {
      int f4 = i*256 + tid; int r = f4 >> 4; int c = (f4 & 15) << 2;
      float4 v = *(const float4*)(Kp + (size_t)(b*SEQ + ch*64 + r)*D_MODEL + h*DKH + c);
      uint4 u; u.x=f2tf32(v.x); u.y=f2tf32(v.y); u.z=f2tf32(v.z); u.w=f2tf32(v.w);
      *(uint4*)(Kc + r*AP_PAD + c) = u;
    }
    {
      const float* vb = Vcol + (size_t)(ch*64 + vk0)*D_MODEL;
      #pragma unroll
      for (int g8 = 0; g8 < 4; g8++) {
        uint4 u;
        u.x = f2tf32(vb[(size_t)(g8*4+0)*D_MODEL]);
        u.y = f2tf32(vb[(size_t)(g8*4+1)*D_MODEL]);
        u.z = f2tf32(vb[(size_t)(g8*4+2)*D_MODEL]);
        u.w = f2tf32(vb[(size_t)(g8*4+3)*D_MODEL]);
        *(uint4*)(Vt + vn*AP_PAD + vk0 + g8*4) = u;
      }
    }
    __syncthreads();

    float sacc[2][4][4];
    #pragma unroll
    for (int mt = 0; mt < 2; mt++)
      #pragma unroll
      for (int nt = 0; nt < 4; nt++)
        #pragma unroll
        for (int j = 0; j < 4; j++) sacc[mt][nt][j] = 0.f;
    #pragma unroll
    for (int kk = 0; kk < 8; kk++) {
      unsigned af[2][4];
      #pragma unroll
      for (int mt = 0; mt < 2; mt++)
        ldsm4(af[mt][0], af[mt][1], af[mt][2], af[mt][3],
              qsb + ((unsigned)((aRowQ + mt*16)*AP_PAD + aCol + kk*8) << 2));
      unsigned bf[4][2];
      #pragma unroll
      for (int np = 0; np < 2; np++) {
        unsigned r0, r1, r2, r3;
        ldsm4(r0, r1, r2, r3, kcb + ((unsigned)((bRowK + np*16)*AP_PAD + bColK + kk*8) << 2));
        bf[2*np][0]=r0; bf[2*np][1]=r1; bf[2*np+1][0]=r2; bf[2*np+1][1]=r3;
      }
      #pragma unroll
      for (int mt = 0; mt < 2; mt++)
        #pragma unroll
        for (int nt = 0; nt < 4; nt++)
          mma_tf32(sacc[mt][nt][0], sacc[mt][nt][1], sacc[mt][nt][2], sacc[mt][nt][3],
                   af[mt][0], af[mt][1], af[mt][2], af[mt][3], bf[nt][0], bf[nt][1]);
    }

    #pragma unroll
    for (int mt = 0; mt < 2; mt++) {
      int r0 = wr*32 + mt*16 + (lane >> 2);
      float2 ms0 = rst[r0];
      float2 ms1 = rst[r0 + 8];
      #pragma unroll
      for (int nt = 0; nt < 4; nt++) {
        int c = wc*32 + nt*8 + qd*2;
        float p0 = fast_exp(sacc[mt][nt][0] - ms0.x) * ms0.y;
        float p1 = fast_exp(sacc[mt][nt][1] - ms0.x) * ms0.y;
        float p2 = fast_exp(sacc[mt][nt][2] - ms1.x) * ms1.y;
        float p3 = fast_exp(sacc[mt][nt][3] - ms1.x) * ms1.y;
        *(float2*)(Abase + (size_t)r0*SEQ + ch*64 + c)       = make_float2(p0, p1);
        *(float2*)(Abase + (size_t)(r0 + 8)*SEQ + ch*64 + c) = make_float2(p2, p3);
        uint2 u0 = make_uint2(f2tf32(p0), f2tf32(p1));
        uint2 u1 = make_uint2(f2tf32(p2), f2tf32(p3));
        *(uint2*)(Ps + r0*AP_PAD + c)       = u0;
        *(uint2*)(Ps + (r0 + 8)*AP_PAD + c) = u1;
      }
    }
    __syncthreads();

    #pragma unroll
    for (int kk = 0; kk < 8; kk++) {
      unsigned af[2][4];
      #pragma unroll
      for (int mt = 0; mt < 2; mt++)
        ldsm4(af[mt][0], af[mt][1], af[mt][2], af[mt][3],
              psb + ((unsigned)((aRowQ + mt*16)*AP_PAD + aCol + kk*8) << 2));
      unsigned bf[4][2];
      #pragma unroll
      for (int np = 0; np < 2; np++) {
        unsigned r0, r1, r2, r3;
        ldsm4(r0, r1, r2, r3, vtb + ((unsigned)((wc*32 + np*16 + bRowV)*AP_PAD + bColV + kk*8) << 2));
        bf[2*np][0]=r0; bf[2*np][1]=r1; bf[2*np+1][0]=r2; bf[2*np+1][1]=r3;
      }
      #pragma unroll
      for (int mt = 0; mt < 2; mt++)
        #pragma unroll
        for (int nt = 0; nt < 4; nt++)
          mma_tf32(oacc[mt][nt][0], oacc[mt][nt][1], oacc[mt][nt][2], oacc[mt][nt][3],
                   af[mt][0], af[mt][1], af[mt][2], af[mt][3], bf[nt][0], bf[nt][1]);
    }
  }

  #pragma unroll
  for (int mt = 0; mt < 2; mt++) {
    const int q = bm0 + wr*32 + mt*16 + (lane >> 2);
    #pragma unroll
    for (int nt = 0; nt < 4; nt++) {
      int c = h*DKH + wc*32 + nt*8 + qd*2;
      *(float2*)(ctx + (size_t)(b*SEQ + q)*D_MODEL + c)     = make_float2(oacc[mt][nt][0], oacc[mt][nt][1]);
      *(float2*)(ctx + (size_t)(b*SEQ + q + 8)*D_MODEL + c) = make_float2(oacc[mt][nt][2], oacc[mt][nt][3]);
    }
  }
}

// ================= launch =================
extern "C" void kernel_launch(void* const* d_in, const int* in_sizes, int n_in,
                              void* d_out, int out_size)
{
  const float* q  = (const float*)d_in[0];
  const float* k  = (const float*)d_in[1];
  const float* v  = (const float*)d_in[2];
  const float* Wq = (const float*)d_in[3];
  const float* bq = (const float*)d_in[4];
  const float* Wk = (const float*)d_in[5];
  const float* bk = (const float*)d_in[6];
  const float* Wv = (const float*)d_in[7];
  const float* bv = (const float*)d_in[8];
  const float* Wo = (const float*)d_in[9];
  const float* bo = (const float*)d_in[10];

  float* out  = (float*)d_out;                 // (out, attention) concatenated
  float* attn = out + OUT_ELEMS;

  void *pq, *pk, *pv, *pctx, *pxt, *pwt, *pct;
  cudaGetSymbolAddress(&pq,   g_q);
  cudaGetSymbolAddress(&pk,   g_k);
  cudaGetSymbolAddress(&pv,   g_v);
  cudaGetSymbolAddress(&pctx, g_ctx);
  cudaGetSymbolAddress(&pxt,  g_xt);
  cudaGetSymbolAddress(&pwt,  g_wt);
  cudaGetSymbolAddress(&pct,  g_ctxt);

  cudaFuncSetAttribute(gemm_tf32_kernel, cudaFuncAttributeMaxDynamicSharedMemorySize, GEMM_SMEM_BYTES);
  cudaFuncSetAttribute(qkv_gemm_kernel,  cudaFuncAttributeMaxDynamicSharedMemorySize, GEMM_SMEM_BYTES);
  cudaFuncSetAttribute(stats2_kernel,    cudaFuncAttributeMaxDynamicSharedMemorySize, S2_SMEM);
  cudaFuncSetAttribute(apv_kernel,       cudaFuncAttributeMaxDynamicSharedMemorySize, APV_SMEM);

  // pre-convert GEMM operands to tf32 bits
  dim3 gx(8192, 3);  cvt_x_kernel<<<gx, 256>>>(q, k, v);
  dim3 gw(1024, 4);  cvt_w_kernel<<<gw, 256>>>(Wq, Wk, Wv, Wo);

  dim3 gq(D_MODEL/GBN, MROWS/GBM, 3);          // (8, 64, 3) fused QKV
  qkv_gemm_kernel<<<gq, 128, GEMM_SMEM_BYTES>>>((const float*)pxt, (const float*)pwt,
                                                bq, bk, bv,
                                                (float*)pq, (float*)pk, (float*)pv);

  dim3 gs(SEQ/128, BATCH*NHEAD);               // (8, 128)
  stats2_kernel<<<gs, 256, S2_SMEM>>>((const float*)pq, (const float*)pk);

  dim3 gp(SEQ/128, BATCH*NHEAD);               // (8, 128)
  apv_kernel<<<gp, 256, APV_SMEM>>>((const float*)pq, (const float*)pk, (const float*)pv,
                                    attn, (float*)pctx);

  cvt_c_kernel<<<8192, 256>>>();

  dim3 gg(D_MODEL/GBN, MROWS/GBM);             // (8, 64)
  gemm_tf32_kernel<<<gg, 128, GEMM_SMEM_BYTES>>>((const float*)pct,
                                                 (const float*)pwt + 3*D_MODEL*D_MODEL,
                                                 bo, out);
}

// round 16
// speedup vs baseline: 1.4107x; 1.4107x over previous
#include <cuda_runtime.h>
#include <cstdint>

#define D_MODEL 1024
#define NHEAD   16
#define DKH     64
#define BATCH   8
#define SEQ     1024
#define MROWS   (BATCH*SEQ)                   // 8192
#define OUT_ELEMS  (MROWS*D_MODEL)            // 8388608
#define ATTN_ELEMS (BATCH*NHEAD*SEQ*SEQ)      // 134217728
#define NROWS_TOT  (BATCH*NHEAD*SEQ)          // 131072 attention rows

// ---------------- scratch (no cudaMalloc allowed) ----------------
__device__ float g_q  [MROWS*D_MODEL];
__device__ float g_k  [MROWS*D_MODEL];
__device__ float g_v  [MROWS*D_MODEL];
__device__ float g_ctx[MROWS*D_MODEL];
__device__ float2 g_rowstat[NROWS_TOT];       // per row (M, 1/S)

// ---------------- helpers ----------------
__device__ __forceinline__ unsigned f2tf32(float f){
  unsigned r; asm("cvt.rna.tf32.f32 %0, %1;" : "=r"(r) : "f"(f)); return r;
}
__device__ __forceinline__ uint32_t smem_u32(const void* p){
  return (uint32_t)__cvta_generic_to_shared(p);
}
__device__ __forceinline__ void ldsm4(unsigned &r0, unsigned &r1, unsigned &r2, unsigned &r3, uint32_t a){
  asm volatile("ldmatrix.sync.aligned.m8n8.x4.shared.b16 {%0,%1,%2,%3}, [%4];"
    : "=r"(r0),"=r"(r1),"=r"(r2),"=r"(r3) : "r"(a));
}
__device__ __forceinline__ void mma_tf32(float &d0,float &d1,float &d2,float &d3,
    unsigned a0,unsigned a1,unsigned a2,unsigned a3, unsigned b0,unsigned b1){
  asm volatile("mma.sync.aligned.m16n8k8.row.col.f32.tf32.tf32.f32 "
    "{%0,%1,%2,%3}, {%4,%5,%6,%7}, {%8,%9}, {%0,%1,%2,%3};"
    : "+f"(d0),"+f"(d1),"+f"(d2),"+f"(d3)
    : "r"(a0),"r"(a1),"r"(a2),"r"(a3),"r"(b0),"r"(b1));
}
// FFMA-only exp (avoids MUFU rt=8 for 134M exps). Valid for x <= 0 after max-sub.
__device__ __forceinline__ float fast_exp(float x){
  x = fmaxf(x, -80.f);
  float z  = fmaf(x, 1.4426950408889634f, 12582912.f);
  int   n  = __float_as_int(z) - 0x4B400000;
  float fn = z - 12582912.f;
  float t  = fmaf(x, 1.4426950408889634f, -fn);
  float u  = t * 0.6931471805599453f;
  float p  = fmaf(u, 0.0083333333f, 0.0416666667f);
  p = fmaf(u, p, 0.1666666667f);
  p = fmaf(u, p, 0.5f);
  p = fmaf(u, p, 1.0f);
  p = fmaf(u, p, 1.0f);
  return __int_as_float((n + 127) << 23) * p;
}

// ================= TF32 GEMM (R14: 4 warps, warp tile 64x64) =================
// C[8192,1024] = A @ W^T + bias. CTA tile 128x128, 128 threads.
#define GBM 128
#define GBN 128
#define GBK 32
#define GPAD 36
#define GEMM_SMEM_BYTES (4*GBM*GPAD*4)
#define GK 1024
#define GN 1024

__device__ __forceinline__ void gemm_body(const float* __restrict__ A,
                                          const float* __restrict__ W,
                                          const float* __restrict__ bias,
                                          float* __restrict__ C, float* sm)
{
  float* As = sm;
  float* Ws = sm + 2*GBM*GPAD;
  const int tid = threadIdx.x, lane = tid & 31, wid = tid >> 5;
  const int wr = wid & 1, wc = wid >> 1;          // 2x2 warp grid, warp tile 64x64
  const int bm0 = blockIdx.y * GBM, bn0 = blockIdx.x * GBN;
  const int qg = lane >> 3, lr = lane & 7;
  const int aRow = wr*64 + (qg & 1)*8 + lr;       // + mt*16, mt 0..3
  const int aCol = (qg >> 1)*4;
  const int bRow = wc*64 + (qg >> 1)*8 + lr;      // + np*16, np 0..3
  const int bCol = (qg & 1)*4;

  float acc[4][8][4];
  #pragma unroll
  for (int mt = 0; mt < 4; mt++)
    #pragma unroll
    for (int nt = 0; nt < 8; nt++)
      #pragma unroll
      for (int j = 0; j < 4; j++) acc[mt][nt][j] = 0.f;

  float4 ra[8], rw[8];
  const int nT = GK / GBK;

  #pragma unroll
  for (int i = 0; i < 8; i++) {                   // prologue LDG tile 0
    int f4 = i*128 + tid; int r = f4 >> 3; int c = (f4 & 7) << 2;
    ra[i] = *(const float4*)(A + (size_t)(bm0 + r)*GK + c);
    rw[i] = *(const float4*)(W + (size_t)(bn0 + r)*GK + c);
  }

  for (int t = 0; t < nT; t++) {
    float* as = As + (t & 1)*GBM*GPAD;
    float* ws = Ws + (t & 1)*GBM*GPAD;
    #pragma unroll
    for (int i = 0; i < 8; i++) {                 // fused fp32->tf32 + STS.128
      int f4 = i*128 + tid; int r = f4 >> 3; int c = (f4 & 7) << 2;
      uint4 ua; ua.x=f2tf32(ra[i].x); ua.y=f2tf32(ra[i].y); ua.z=f2tf32(ra[i].z); ua.w=f2tf32(ra[i].w);
      uint4 uw; uw.x=f2tf32(rw[i].x); uw.y=f2tf32(rw[i].y); uw.z=f2tf32(rw[i].z); uw.w=f2tf32(rw[i].w);
      *(uint4*)(as + r*GPAD + c) = ua;
      *(uint4*)(ws + r*GPAD + c) = uw;
    }
    __syncthreads();
    if (t + 1 < nT) {                             // prefetch next tile (overlaps mma)
      int k0 = (t + 1)*GBK;
      #pragma unroll
      for (int i = 0; i < 8; i++) {
        int f4 = i*128 + tid; int r = f4 >> 3; int c = (f4 & 7) << 2;
        ra[i] = *(const float4*)(A + (size_t)(bm0 + r)*GK + k0 + c);
        rw[i] = *(const float4*)(W + (size_t)(bn0 + r)*GK + k0 + c);
      }
    }
    uint32_t asb = smem_u32(as), wsb = smem_u32(ws);
    #pragma unroll
    for (int kk = 0; kk < 4; kk++) {
      unsigned af[4][4];
      #pragma unroll
      for (int mt = 0; mt < 4; mt++)
        ldsm4(af[mt][0], af[mt][1], af[mt][2], af[mt][3],
              asb + ((unsigned)((aRow + mt*16)*GPAD + aCol + kk*8) << 2));
      unsigned bf[8][2];
      #pragma unroll
      for (int np = 0; np < 4; np++) {
        unsigned r0, r1, r2, r3;
        ldsm4(r0, r1, r2, r3, wsb + ((unsigned)((bRow + np*16)*GPAD + bCol + kk*8) << 2));
        bf[2*np][0]=r0; bf[2*np][1]=r1; bf[2*np+1][0]=r2; bf[2*np+1][1]=r3;
      }
      #pragma unroll
      for (int mt = 0; mt < 4; mt++)
        #pragma unroll
        for (int nt = 0; nt < 8; nt++)
          mma_tf32(acc[mt][nt][0], acc[mt][nt][1], acc[mt][nt][2], acc[mt][nt][3],
                   af[mt][0], af[mt][1], af[mt][2], af[mt][3], bf[nt][0], bf[nt][1]);
    }
  }

  #pragma unroll
  for (int mt = 0; mt < 4; mt++)
    #pragma unroll
    for (int nt = 0; nt < 8; nt++) {
      int r = bm0 + wr*64 + mt*16 + (lane >> 2);
      int c = bn0 + wc*64 + nt*8 + (lane & 3)*2;
      float2 bb = *(const float2*)(bias + c);
      float2 v0 = make_float2(acc[mt][nt][0] + bb.x, acc[mt][nt][1] + bb.y);
      float2 v1 = make_float2(acc[mt][nt][2] + bb.x, acc[mt][nt][3] + bb.y);
      *(float2*)(C + (size_t)r*GN + c)       = v0;
      *(float2*)(C + (size_t)(r + 8)*GN + c) = v1;
    }
}

__global__ void __launch_bounds__(128, 2)
gemm_tf32_kernel(const float* __restrict__ A, const float* __restrict__ W,
                 const float* __restrict__ bias, float* __restrict__ C)
{
  extern __shared__ float sm[];
  gemm_body(A, W, bias, C, sm);
}

// QKV fused: blockIdx.z selects which projection.
__global__ void __launch_bounds__(128, 2)
qkv_gemm_kernel(const float* __restrict__ q, const float* __restrict__ k,
                const float* __restrict__ v,
                const float* __restrict__ Wq, const float* __restrict__ Wk,
                const float* __restrict__ Wv,
                const float* __restrict__ bq, const float* __restrict__ bk,
                const float* __restrict__ bv,
                float* __restrict__ Cq, float* __restrict__ Ck, float* __restrict__ Cv)
{
  extern __shared__ float sm[];
  const float *A, *W, *bias; float* C;
  if (blockIdx.z == 0)      { A = q; W = Wq; bias = bq; C = Cq; }
  else if (blockIdx.z == 1) { A = k; W = Wk; bias = bk; C = Ck; }
  else                      { A = v; W = Wv; bias = bv; C = Cv; }
  gemm_body(A, W, bias, C, sm);
}

// ======== stats2 (UNCHANGED from passing R13/R14): per-row softmax stats ========
#define S2_PAD 68
#define S2_RED (2*128*S2_PAD)               // mp[256] then sp[256]
#define S2_SMEM ((S2_RED + 512)*4)          // 71,680 B

__global__ __launch_bounds__(256)
void stats2_kernel(const float* __restrict__ Qp, const float* __restrict__ Kp)
{
  extern __shared__ float sm[];
  float* Qs = sm;                     // [128][68] q-rows (pre-scaled 1/8), tf32
  float* Ks = sm + 128*S2_PAD;        // [128][68] k-chunk rows, tf32
  float* mp = sm + S2_RED;            // [256]
  float* sp = mp + 256;               // [256]
  const int tid = threadIdx.x, lane = tid & 31, wid = tid >> 5;
  const int wr = wid & 3, wc = wid >> 2;
  const int bh = blockIdx.y, b = bh >> 4, h = bh & 15;
  const int bm0 = blockIdx.x * 128;
  const int qg = lane >> 3, lr = lane & 7;
  const int aRow = wr*32 + (qg & 1)*8 + lr;
  const int aCol = (qg >> 1)*4;
  const int bRow = wc*64 + (qg >> 1)*8 + lr;
  const int bCol = (qg & 1)*4;

  #pragma unroll
  for (int i = 0; i < 8; i++) {
    int f4 = i*256 + tid; int r = f4 >> 4; int c = (f4 & 15) << 2;
    float4 v = *(const float4*)(Qp + (size_t)(b*SEQ + bm0 + r)*D_MODEL + h*DKH + c);
    uint4 u; u.x=f2tf32(0.125f*v.x); u.y=f2tf32(0.125f*v.y);
             u.z=f2tf32(0.125f*v.z); u.w=f2tf32(0.125f*v.w);
    *(uint4*)(Qs + r*S2_PAD + c) = u;
  }

  float runM = -1e30f, runS = 0.f;    // threads tid<128 own row `tid`
  uint32_t qsb = smem_u32(Qs), ksb = smem_u32(Ks);

  for (int ch = 0; ch < 8; ch++) {
    __syncthreads();
    #pragma unroll
    for (int i = 0; i < 8; i++) {
      int f4 = i*256 + tid; int r = f4 >> 4; int c = (f4 & 15) << 2;
      float4 v = *(const float4*)(Kp + (size_t)(b*SEQ + ch*128 + r)*D_MODEL + h*DKH + c);
      uint4 u; u.x=f2tf32(v.x); u.y=f2tf32(v.y); u.z=f2tf32(v.z); u.w=f2tf32(v.w);
      *(uint4*)(Ks + r*S2_PAD + c) = u;
    }
    __syncthreads();

    float acc[2][8][4];
    #pragma unroll
    for (int mt = 0; mt < 2; mt++)
      #pragma unroll
      for (int nt = 0; nt < 8; nt++)
        #pragma unroll
        for (int j = 0; j < 4; j++) acc[mt][nt][j] = 0.f;

    #pragma unroll
    for (int kk = 0; kk < 8; kk++) {
      unsigned af[2][4];
      #pragma unroll
      for (int mt = 0; mt < 2; mt++)
        ldsm4(af[mt][0], af[mt][1], af[mt][2], af[mt][3],
              qsb + ((unsigned)((aRow + mt*16)*S2_PAD + aCol + kk*8) << 2));
      unsigned bf[8][2];
      #pragma unroll
      for (int np = 0; np < 4; np++) {
        unsigned r0, r1, r2, r3;
        ldsm4(r0, r1, r2, r3, ksb + ((unsigned)((bRow + np*16)*S2_PAD + bCol + kk*8) << 2));
        bf[2*np][0]=r0; bf[2*np][1]=r1; bf[2*np+1][0]=r2; bf[2*np+1][1]=r3;
      }
      #pragma unroll
      for (int mt = 0; mt < 2; mt++)
        #pragma unroll
        for (int nt = 0; nt < 8; nt++)
          mma_tf32(acc[mt][nt][0], acc[mt][nt][1], acc[mt][nt][2], acc[mt][nt][3],
                   af[mt][0], af[mt][1], af[mt][2], af[mt][3], bf[nt][0], bf[nt][1]);
    }

    #pragma unroll
    for (int mt = 0; mt < 2; mt++)
      #pragma unroll
      for (int hh = 0; hh < 2; hh++) {
        float m = -1e30f;
        #pragma unroll
        for (int nt = 0; nt < 8; nt++)
          m = fmaxf(m, fmaxf(acc[mt][nt][2*hh], acc[mt][nt][2*hh+1]));
        #pragma unroll
        for (int off = 1; off <= 2; off <<= 1)
          m = fmaxf(m, __shfl_xor_sync(0xffffffffu, m, off));
        if ((lane & 3) == 0)
          mp[wc*128 + wr*32 + mt*16 + hh*8 + (lane >> 2)] = m;
      }
    __syncthreads();
    #pragma unroll
    for (int mt = 0; mt < 2; mt++)
      #pragma unroll
      for (int hh = 0; hh < 2; hh++) {
        int rl = wr*32 + mt*16 + hh*8 + (lane >> 2);
        float m = fmaxf(mp[rl], mp[128 + rl]);
        float s = 0.f;
        #pragma unroll
        for (int nt = 0; nt < 8; nt++)
          s += fast_exp(acc[mt][nt][2*hh] - m) + fast_exp(acc[mt][nt][2*hh+1] - m);
        #pragma unroll
        for (int off = 1; off <= 2; off <<= 1)
          s += __shfl_xor_sync(0xffffffffu, s, off);
        if ((lane & 3) == 0) sp[wc*128 + rl] = s;
      }
    __syncthreads();
    if (tid < 128) {
      float m_c = fmaxf(mp[tid], mp[128 + tid]);
      float s_c = sp[tid] + sp[128 + tid];
      float Mn  = fmaxf(runM, m_c);
      runS = runS * fast_exp(runM - Mn) + s_c * fast_exp(m_c - Mn);
      runM = Mn;
    }
  }

  if (tid < 128)
    g_rowstat[(size_t)bh*SEQ + bm0 + tid] = make_float2(runM, 1.f / runS);
}

// ======== fused apv (UNCHANGED from passing R11/R13/R14) ========
#define AP_PAD 68
#define AP_Q   0
#define AP_K   (128*AP_PAD)
#define AP_V   (AP_K + 64*AP_PAD)
#define AP_P   (AP_V + 64*AP_PAD)
#define AP_RST (AP_P + 128*AP_PAD)
#define APV_SMEM ((AP_RST + 256)*4)       // 105,472 B

__global__ void __launch_bounds__(256, 2)
apv_kernel(const float* __restrict__ Qp, const float* __restrict__ Kp,
           const float* __restrict__ Vp,
           float* __restrict__ attn, float* __restrict__ ctx)
{
  extern __shared__ float sm[];
  float*  Qs  = sm + AP_Q;
  float*  Kc  = sm + AP_K;
  float*  Vt  = sm + AP_V;
  float*  Ps  = sm + AP_P;
  float2* rst = (float2*)(sm + AP_RST);
  const int tid = threadIdx.x, lane = tid & 31, wid = tid >> 5;
  const int bh = blockIdx.y, b = bh >> 4, h = bh & 15;
  const int bm0 = blockIdx.x * 128;
  const int qg = lane >> 3, lr = lane & 7;
  const int qd = lane & 3;
  const int wr = wid & 3, wc = wid >> 2;
  const int aRowQ = wr*32 + (qg & 1)*8 + lr;
  const int aCol  = (qg >> 1)*4;
  const int bRowK = wc*32 + (qg >> 1)*8 + lr;
  const int bColK = (qg & 1)*4;
  const int bRowV = (qg >> 1)*8 + lr;
  const int bColV = (qg & 1)*4;
  const int vn  = tid & 63;
  const int vk0 = (tid >> 6) * 16;

  if (tid < 128) rst[tid] = g_rowstat[(size_t)bh*SEQ + bm0 + tid];

  #pragma unroll
  for (int i = 0; i < 8; i++) {
    int f4 = i*256 + tid; int r = f4 >> 4; int c = (f4 & 15) << 2;
    float4 v = *(const float4*)(Qp + (size_t)(b*SEQ + bm0 + r)*D_MODEL + h*DKH + c);
    uint4 u; u.x=f2tf32(0.125f*v.x); u.y=f2tf32(0.125f*v.y);
             u.z=f2tf32(0.125f*v.z); u.w=f2tf32(0.125f*v.w);
    *(uint4*)(Qs + r*AP_PAD + c) = u;
  }

  float* Abase = attn + (size_t)bh*SEQ*SEQ + (size_t)bm0*SEQ;
  const float* Vcol = Vp + (size_t)(b*SEQ)*D_MODEL + h*DKH + vn;

  float oacc[2][4][4];
  #pragma unroll
  for (int mt = 0; mt < 2; mt++)
    #pragma unroll
    for (int nt = 0; nt < 4; nt++)
      #pragma unroll
      for (int j = 0; j < 4; j++) oacc[mt][nt][j] = 0.f;

  uint32_t qsb = smem_u32(Qs), kcb = smem_u32(Kc), vtb = smem_u32(Vt), psb = smem_u32(Ps);

  for (int ch = 0; ch < 16; ch++) {
    __syncthreads();
    #pragma unroll
    for (int i = 0; i < 4; i++) {
      int f4 = i*256 + tid; int r = f4 >> 4; int c = (f4 & 15) << 2;
      float4 v = *(const float4*)(Kp + (size_t)(b*SEQ + ch*64 + r)*D_MODEL + h*DKH + c);
      uint4 u; u.x=f2tf32(v.x); u.y=f2tf32(v.y); u.z=f2tf32(v.z); u.w=f2tf32(v.w);
      *(uint4*)(Kc + r*AP_PAD + c) = u;
    }
    {
      const float* vb = Vcol + (size_t)(ch*64 + vk0)*D_MODEL;
      #pragma unroll
      for (int g8 = 0; g8 < 4; g8++) {
        uint4 u;
        u.x = f2tf32(vb[(size_t)(g8*4+0)*D_MODEL]);
        u.y = f2tf32(vb[(size_t)(g8*4+1)*D_MODEL]);
        u.z = f2tf32(vb[(size_t)(g8*4+2)*D_MODEL]);
        u.w = f2tf32(vb[(size_t)(g8*4+3)*D_MODEL]);
        *(uint4*)(Vt + vn*AP_PAD + vk0 + g8*4) = u;
      }
    }
    __syncthreads();

    float sacc[2][4][4];
    #pragma unroll
    for (int mt = 0; mt < 2; mt++)
      #pragma unroll
      for (int nt = 0; nt < 4; nt++)
        #pragma unroll
        for (int j = 0; j < 4; j++) sacc[mt][nt][j] = 0.f;
    #pragma unroll
    for (int kk = 0; kk < 8; kk++) {
      unsigned af[2][4];
      #pragma unroll
      for (int mt = 0; mt < 2; mt++)
        ldsm4(af[mt][0], af[mt][1], af[mt][2], af[mt][3],
              qsb + ((unsigned)((aRowQ + mt*16)*AP_PAD + aCol + kk*8) << 2));
      unsigned bf[4][2];
      #pragma unroll
      for (int np = 0; np < 2; np++) {
        unsigned r0, r1, r2, r3;
        ldsm4(r0, r1, r2, r3, kcb + ((unsigned)((bRowK + np*16)*AP_PAD + bColK + kk*8) << 2));
        bf[2*np][0]=r0; bf[2*np][1]=r1; bf[2*np+1][0]=r2; bf[2*np+1][1]=r3;
      }
      #pragma unroll
      for (int mt = 0; mt < 2; mt++)
        #pragma unroll
        for (int nt = 0; nt < 4; nt++)
          mma_tf32(sacc[mt][nt][0], sacc[mt][nt][1], sacc[mt][nt][2], sacc[mt][nt][3],
                   af[mt][0], af[mt][1], af[mt][2], af[mt][3], bf[nt][0], bf[nt][1]);
    }

    #pragma unroll
    for (int mt = 0; mt < 2; mt++) {
      int r0 = wr*32 + mt*16 + (lane >> 2);
      float2 ms0 = rst[r0];
      float2 ms1 = rst[r0 + 8];
      #pragma unroll
      for (int nt = 0; nt < 4; nt++) {
        int c = wc*32 + nt*8 + qd*2;
        float p0 = fast_exp(sacc[mt][nt][0] - ms0.x) * ms0.y;
        float p1 = fast_exp(sacc[mt][nt][1] - ms0.x) * ms0.y;
        float p2 = fast_exp(sacc[mt][nt][2] - ms1.x) * ms1.y;
        float p3 = fast_exp(sacc[mt][nt][3] - ms1.x) * ms1.y;
        *(float2*)(Abase + (size_t)r0*SEQ + ch*64 + c)       = make_float2(p0, p1);
        *(float2*)(Abase + (size_t)(r0 + 8)*SEQ + ch*64 + c) = make_float2(p2, p3);
        uint2 u0 = make_uint2(f2tf32(p0), f2tf32(p1));
        uint2 u1 = make_uint2(f2tf32(p2), f2tf32(p3));
        *(uint2*)(Ps + r0*AP_PAD + c)       = u0;
        *(uint2*)(Ps + (r0 + 8)*AP_PAD + c) = u1;
      }
    }
    __syncthreads();

    #pragma unroll
    for (int kk = 0; kk < 8; kk++) {
      unsigned af[2][4];
      #pragma unroll
      for (int mt = 0; mt < 2; mt++)
        ldsm4(af[mt][0], af[mt][1], af[mt][2], af[mt][3],
              psb + ((unsigned)((aRowQ + mt*16)*AP_PAD + aCol + kk*8) << 2));
      unsigned bf[4][2];
      #pragma unroll
      for (int np = 0; np < 2; np++) {
        unsigned r0, r1, r2, r3;
        ldsm4(r0, r1, r2, r3, vtb + ((unsigned)((wc*32 + np*16 + bRowV)*AP_PAD + bColV + kk*8) << 2));
        bf[2*np][0]=r0; bf[2*np][1]=r1; bf[2*np+1][0]=r2; bf[2*np+1][1]=r3;
      }
      #pragma unroll
      for (int mt = 0; mt < 2; mt++)
        #pragma unroll
        for (int nt = 0; nt < 4; nt++)
          mma_tf32(oacc[mt][nt][0], oacc[mt][nt][1], oacc[mt][nt][2], oacc[mt][nt][3],
                   af[mt][0], af[mt][1], af[mt][2], af[mt][3], bf[nt][0], bf[nt][1]);
    }
  }

  #pragma unroll
  for (int mt = 0; mt < 2; mt++) {
    const int q = bm0 + wr*32 + mt*16 + (lane >> 2);
    #pragma unroll
    for (int nt = 0; nt < 4; nt++) {
      int c = h*DKH + wc*32 + nt*8 + qd*2;
      *(float2*)(ctx + (size_t)(b*SEQ + q)*D_MODEL + c)     = make_float2(oacc[mt][nt][0], oacc[mt][nt][1]);
      *(float2*)(ctx + (size_t)(b*SEQ + q + 8)*D_MODEL + c) = make_float2(oacc[mt][nt][2], oacc[mt][nt][3]);
    }
  }
}

// ================= launch =================
extern "C" void kernel_launch(void* const* d_in, const int* in_sizes, int n_in,
                              void* d_out, int out_size)
{
  const float* q  = (const float*)d_in[0];
  const float* k  = (const float*)d_in[1];
  const float* v  = (const float*)d_in[2];
  const float* Wq = (const float*)d_in[3];
  const float* bq = (const float*)d_in[4];
  const float* Wk = (const float*)d_in[5];
  const float* bk = (const float*)d_in[6];
  const float* Wv = (const float*)d_in[7];
  const float* bv = (const float*)d_in[8];
  const float* Wo = (const float*)d_in[9];
  const float* bo = (const float*)d_in[10];

  float* out  = (float*)d_out;                 // (out, attention) concatenated
  float* attn = out + OUT_ELEMS;

  void *pq, *pk, *pv, *pctx;
  cudaGetSymbolAddress(&pq,   g_q);
  cudaGetSymbolAddress(&pk,   g_k);
  cudaGetSymbolAddress(&pv,   g_v);
  cudaGetSymbolAddress(&pctx, g_ctx);

  cudaFuncSetAttribute(gemm_tf32_kernel, cudaFuncAttributeMaxDynamicSharedMemorySize, GEMM_SMEM_BYTES);
  cudaFuncSetAttribute(qkv_gemm_kernel,  cudaFuncAttributeMaxDynamicSharedMemorySize, GEMM_SMEM_BYTES);
  cudaFuncSetAttribute(stats2_kernel,    cudaFuncAttributeMaxDynamicSharedMemorySize, S2_SMEM);
  cudaFuncSetAttribute(apv_kernel,       cudaFuncAttributeMaxDynamicSharedMemorySize, APV_SMEM);

  dim3 gq(D_MODEL/GBN, MROWS/GBM, 3);          // (8, 64, 3) fused QKV, 128-thread CTAs
  qkv_gemm_kernel<<<gq, 128, GEMM_SMEM_BYTES>>>(q, k, v, Wq, Wk, Wv, bq, bk, bv,
                                                (float*)pq, (float*)pk, (float*)pv);

  dim3 gs(SEQ/128, BATCH*NHEAD);               // (8, 128) one CTA per 128 rows
  stats2_kernel<<<gs, 256, S2_SMEM>>>((const float*)pq, (const float*)pk);

  dim3 gp(SEQ/128, BATCH*NHEAD);               // (8, 128)
  apv_kernel<<<gp, 256, APV_SMEM>>>((const float*)pq, (const float*)pk, (const float*)pv,
                                    attn, (float*)pctx);

  dim3 gg(D_MODEL/GBN, MROWS/GBM);             // (8, 64)
  gemm_tf32_kernel<<<gg, 128, GEMM_SMEM_BYTES>>>((const float*)pctx, Wo, bo, out);
}